// round 14
// baseline (speedup 1.0000x reference)
#include <cuda_runtime.h>
#include <cuda_bf16.h>
#include <cuda_fp16.h>
#include <cstdint>

#define NN 25000
#define EE 400000
#define TILES64 (EE / 64)   // 6250

typedef unsigned long long ull;

// ---- scratch (static device globals; no allocation) ----
__device__ float g_node_score[NN];
__device__ int   g_segmax[NN];
__device__ float g_se[NN];
__device__ float g_agg[(size_t)NN * 128];
__device__ float g_scores[EE];
__device__ float g_ex[EE];
// transposed fp16 weights, K-major [N][K]
__device__ __half g_w1t16[256 * 640];
__device__ __half g_w2t16[128 * 256];

// ---- generic helpers ----
__device__ __forceinline__ ull pk(float lo, float hi) {
    ull r; asm("mov.b64 %0, {%1,%2};" : "=l"(r) : "f"(lo), "f"(hi)); return r;
}
__device__ __forceinline__ float2 upk(ull v) {
    float2 r; asm("mov.b64 {%0,%1}, %2;" : "=f"(r.x), "=f"(r.y) : "l"(v)); return r;
}
__device__ __forceinline__ void fma2(ull& d, ull a, ull b) {
    asm("fma.rn.f32x2 %0, %1, %2, %0;" : "+l"(d) : "l"(a), "l"(b));
}
__device__ __forceinline__ float wred(float v) {
#pragma unroll
    for (int o = 16; o; o >>= 1) v += __shfl_xor_sync(0xffffffffu, v, o);
    return v;
}
__device__ __forceinline__ int f2o(float f) { int i = __float_as_int(f); return i >= 0 ? i : i ^ 0x7fffffff; }
__device__ __forceinline__ float o2f(int i) { return __int_as_float(i >= 0 ? i : i ^ 0x7fffffff); }
__device__ __forceinline__ uint32_t smem_u32(const void* p) {
    uint32_t a; asm("{ .reg .u64 t; cvta.to.shared.u64 t, %1; cvt.u32.u64 %0, t; }" : "=r"(a) : "l"(p));
    return a;
}
__device__ __forceinline__ uint32_t h2u(__half2 h) { return *(uint32_t*)&h; }

// warp-level fp16 MMA (sm_80+ baseline PTX; valid on plain sm_100 target)
__device__ __forceinline__ void mma16816(float* d, const uint32_t* a, uint32_t b0, uint32_t b1) {
    asm volatile(
        "mma.sync.aligned.m16n8k16.row.col.f32.f16.f16.f32 "
        "{%0,%1,%2,%3}, {%4,%5,%6,%7}, {%8,%9}, {%0,%1,%2,%3};"
        : "+f"(d[0]), "+f"(d[1]), "+f"(d[2]), "+f"(d[3])
        : "r"(a[0]), "r"(a[1]), "r"(a[2]), "r"(a[3]), "r"(b0), "r"(b1));
}

// ldmatrix x4 (sm_75+ baseline)
__device__ __forceinline__ void ldmx4(uint32_t* r, uint32_t addr) {
    asm volatile("ldmatrix.sync.aligned.m8n8.x4.shared.b16 {%0,%1,%2,%3}, [%4];"
                 : "=r"(r[0]), "=r"(r[1]), "=r"(r[2]), "=r"(r[3]) : "r"(addr));
}

// ---------------- prep: transpose fp16 weights ----------------
__global__ void k_prep(const float* __restrict__ ew1, const float* __restrict__ ew2) {
    int i = blockIdx.x * 256 + threadIdx.x;
    if (i < 256 * 640) {
        int n = i / 640, k = i - n * 640;
        g_w1t16[i] = __float2half_rn(ew1[(size_t)k * 256 + n]);
    } else {
        int j = i - 256 * 640;
        if (j < 128 * 256) {
            int n = j / 256, k = j - n * 256;
            g_w2t16[j] = __float2half_rn(ew2[(size_t)k * 128 + n]);
        }
    }
}

// ---------------- K0: per-node attention-score part + scratch init ----------------
__global__ void k0_node_prep(const float* __restrict__ nf, const float* __restrict__ aw) {
    int node = blockIdx.x * 8 + (threadIdx.x >> 5);
    int lane = threadIdx.x & 31;
    if (node >= NN) return;
    const float* row = nf + (size_t)node * 256;
    float s = 0.f;
#pragma unroll
    for (int c = lane; c < 256; c += 32) {
        const float4 a = *(const float4*)(aw + c * 4);
        s += row[c] * (a.x + a.y + a.z + a.w);
    }
    s = wred(s);
    if (lane == 0) {
        g_node_score[node] = s * 0.25f;
        g_segmax[node] = (int)0x80000000;
        g_se[node] = 0.f;
    }
    float* ag = g_agg + (size_t)node * 128;
    for (int c = lane; c < 128; c += 32) ag[c] = 0.f;
}

// ---------------- K1: 64-edge tiles, fp16, 2-stage double buffer, occ=2 ----------------
// SMEM (bytes), rows padded to 72 fp16 (144B = 9x16B granules):
//  0:     sidx[64] | 256: didx[64]
//  1024:  A bufs 2 x [64][72]   (2x9216)
//  19456: B bufs 2 x [128][72]  (2x18432)
//  56320: H: 4 K-chunks x [64][72] = 36864   (also X fp32 [64][132] = 33792 in epilogue2)
//  total 93184
#define OFF_A0 1024
#define OFF_B0 19456
#define OFF_H  56320
#define OFF_X  56320
#define SMEM_K1 93184

// single-pass MMA over one 64-K chunk: acc += A*B
__device__ __forceinline__ void mma_chunk1(float acc[2][4][4], uint32_t shA, uint32_t shB) {
#pragma unroll
    for (int ks = 0; ks < 4; ks++) {
        const uint32_t kb2 = ks * 32;  // k bytes
        uint32_t Aa[2][4];
        ldmx4(Aa[0], shA + kb2);
        ldmx4(Aa[1], shA + 2304 + kb2);
#pragma unroll
        for (int ntp = 0; ntp < 2; ntp++) {
            uint32_t b[4];
            ldmx4(b, shB + ntp * 2304 + kb2);
#pragma unroll
            for (int hf = 0; hf < 2; hf++) {
                const int nt = ntp * 2 + hf;
                mma16816(acc[0][nt], Aa[0], b[hf * 2], b[hf * 2 + 1]);
                mma16816(acc[1][nt], Aa[1], b[hf * 2], b[hf * 2 + 1]);
            }
        }
    }
}

__global__ __launch_bounds__(256, 2) void k1_edge_mma(
    const float* __restrict__ nf, const float* __restrict__ ef, const int* __restrict__ ei,
    const float* __restrict__ eb1, const float* __restrict__ eb2,
    const float* __restrict__ eng, const float* __restrict__ enb,
    const float* __restrict__ aw, const float* __restrict__ ab,
    float* __restrict__ e_out) {
    extern __shared__ char smb[];
    int* sidx = (int*)smb;
    int* didx = (int*)(smb + 256);
    const int tid = threadIdx.x;
    const int wid = tid >> 5, lane = tid & 31;
    const int wm = wid >> 2, wn = wid & 3;
    const int m0 = wm * 32;
    const int qr = lane >> 2;         // 0..7
    const int qc = (lane & 3) * 2;    // 0,2,4,6
    const int e0 = blockIdx.x * 64;

    if (tid < 64) sidx[tid] = ei[e0 + tid];
    else if (tid < 128) didx[tid - 64] = ei[EE + e0 + tid - 64];
    __syncthreads();

    // per-lane ldmatrix base addresses (same lane mapping as the passing R13 kernel)
    const uint32_t sbase = smem_u32(smb);
    const int mrow = (lane & 7) + (((lane >> 3) & 1) << 3);
    const uint32_t aOff = (uint32_t)((m0 + mrow) * 144 + ((lane >> 4) << 4));
    const int brow = (lane & 7) + ((lane >> 4) << 3);
    const uint32_t bOff = (uint32_t)((wn * 32 + brow) * 144 + (((lane >> 3) & 1) << 4));
    const uint32_t shA_[2] = { sbase + OFF_A0 + aOff, sbase + OFF_A0 + 9216 + aOff };
    const uint32_t shB_[2] = { sbase + OFF_B0 + bOff, sbase + OFF_B0 + 18432 + bOff };

    // producer prefetch registers
    float4 pfA[4];  // 16 floats: A row slice
    uint4  pfW[4];  // 64 B: B row slice
    const int arow = tid >> 2, akc = (tid & 3) * 16;   // A: 64 rows x (4 thr x 16 floats)
    const int wrow = tid >> 1, wkc = (tid & 1) * 32;   // B: 128 rows x (2 thr x 32 halfs)

    auto ldA = [&](int c) {
        const int kg = c * 64 + akc;
        const float* base;
        if (kg < 256)      base = nf + (size_t)sidx[arow] * 256 + kg;
        else if (kg < 512) base = nf + (size_t)didx[arow] * 256 + (kg - 256);
        else               base = ef + (size_t)(e0 + arow) * 128 + (kg - 512);
#pragma unroll
        for (int g = 0; g < 4; g++) pfA[g] = *(const float4*)(base + g * 4);
    };
    auto ldW1 = [&](int h, int c) {
        const __half* src = g_w1t16 + (size_t)(h * 128 + wrow) * 640 + c * 64 + wkc;
#pragma unroll
        for (int g = 0; g < 4; g++) pfW[g] = *(const uint4*)(src + g * 8);
    };
    auto ldW2 = [&](int c) {
        const __half* src = g_w2t16 + (size_t)wrow * 256 + c * 64 + wkc;
#pragma unroll
        for (int g = 0; g < 4; g++) pfW[g] = *(const uint4*)(src + g * 8);
    };
    auto stA = [&](int s) {
        uint32_t hv[8];
#pragma unroll
        for (int g = 0; g < 4; g++) {
            float4 v = pfA[g];
            hv[g * 2]     = h2u(__floats2half2_rn(v.x, v.y));
            hv[g * 2 + 1] = h2u(__floats2half2_rn(v.z, v.w));
        }
        char* dst = smb + OFF_A0 + s * 9216;
        const uint32_t off = (uint32_t)(arow * 144 + akc * 2);
        *(uint4*)(dst + off)      = make_uint4(hv[0], hv[1], hv[2], hv[3]);
        *(uint4*)(dst + off + 16) = make_uint4(hv[4], hv[5], hv[6], hv[7]);
    };
    auto stW = [&](int s) {
        char* dst = smb + OFF_B0 + s * 18432 + wrow * 144 + wkc * 2;
#pragma unroll
        for (int g = 0; g < 4; g++) *(uint4*)(dst + g * 16) = pfW[g];
    };

    float acc[2][4][4];
#pragma unroll
    for (int mt = 0; mt < 2; mt++)
#pragma unroll
        for (int nt = 0; nt < 4; nt++)
#pragma unroll
            for (int q = 0; q < 4; q++) acc[mt][nt][q] = 0.f;

    // ========= phase 1: 20 chunks, 2-stage double buffer, 1 sync/chunk =========
    // prologue: chunk0 -> buf0; chunk1 -> regs
    ldA(0); ldW1(0, 0);
    stA(0); stW(0);
    ldA(1); ldW1(0, 1);
    __syncthreads();
#pragma unroll 1
    for (int st = 0; st < 20; st++) {
        const int s = st & 1;
        // store chunk st+1 (in regs) to the non-consumed buffer
        if (st < 19) { stA(s ^ 1); stW(s ^ 1); }
        else         { stW(0); }   // W2 chunk 0 -> B buf 0
        // prefetch chunk st+2 (or W2 chunks at the tail)
        if (st < 18)      { ldA((st + 2) % 10); ldW1((st + 2) / 10, (st + 2) % 10); }
        else if (st == 18) ldW2(0);
        else               ldW2(1);
        mma_chunk1(acc, shA_[s], shB_[s]);
        if ((st % 10) == 9) {
            // epilogue 1: bias + relu + fp16 -> H chunk
            const int h = st / 10;
            const int chunk = h * 2 + (wn >> 1);
            char* Hh = smb + OFF_H + chunk * 9216;
#pragma unroll
            for (int mt = 0; mt < 2; mt++)
#pragma unroll
                for (int nt = 0; nt < 4; nt++) {
                    const int gcol = h * 128 + wn * 32 + nt * 8 + qc;
                    const float b0v = eb1[gcol], b1v = eb1[gcol + 1];
                    const int row = m0 + mt * 16 + qr;
                    const int colc = (wn & 1) * 32 + nt * 8 + qc;
                    float f0 = fmaxf(acc[mt][nt][0] + b0v, 0.f);
                    float f1 = fmaxf(acc[mt][nt][1] + b1v, 0.f);
                    *(uint32_t*)(Hh + row * 144 + colc * 2) = h2u(__floats2half2_rn(f0, f1));
                    float f2 = fmaxf(acc[mt][nt][2] + b0v, 0.f);
                    float f3 = fmaxf(acc[mt][nt][3] + b1v, 0.f);
                    *(uint32_t*)(Hh + (row + 8) * 144 + colc * 2) = h2u(__floats2half2_rn(f2, f3));
                }
#pragma unroll
            for (int mt = 0; mt < 2; mt++)
#pragma unroll
                for (int nt = 0; nt < 4; nt++)
#pragma unroll
                    for (int q = 0; q < 4; q++) acc[mt][nt][q] = 0.f;
        }
        __syncthreads();
    }

    // ========= phase 2: H(64x256) @ W2(256x128), double-buffered W2 =========
#pragma unroll 1
    for (int c2 = 0; c2 < 4; c2++) {
        const int s = c2 & 1;
        if (c2 < 3) stW(s ^ 1);     // W2 chunk c2+1 from regs
        if (c2 < 2) ldW2(c2 + 2);
        const uint32_t shH = sbase + OFF_H + c2 * 9216 + aOff;
        mma_chunk1(acc, shH, shB_[s]);
        __syncthreads();
    }

    // ========= epilogue 2: bias + residual -> X, LN, score =========
    float* X = (float*)(smb + OFF_X);
#pragma unroll
    for (int mt = 0; mt < 2; mt++)
#pragma unroll
        for (int nt = 0; nt < 4; nt++) {
            const int col = wn * 32 + nt * 8 + qc;
            const float b0v = eb2[col], b1v = eb2[col + 1];
            const int row = m0 + mt * 16 + qr;
            float2 v0, v1;
            v0.x = acc[mt][nt][0] + b0v + ef[(size_t)(e0 + row) * 128 + col];
            v0.y = acc[mt][nt][1] + b1v + ef[(size_t)(e0 + row) * 128 + col + 1];
            v1.x = acc[mt][nt][2] + b0v + ef[(size_t)(e0 + row + 8) * 128 + col];
            v1.y = acc[mt][nt][3] + b1v + ef[(size_t)(e0 + row + 8) * 128 + col + 1];
            *(float2*)(X + row * 132 + col) = v0;
            *(float2*)(X + (row + 8) * 132 + col) = v1;
        }
    __syncthreads();

    const float abm = 0.25f * (ab[0] + ab[1] + ab[2] + ab[3]);
    const int c4 = lane * 4;
    const float4 g4 = *(const float4*)(eng + c4);
    const float4 b4 = *(const float4*)(enb + c4);
    float4 t0 = *(const float4*)(aw + (256 + c4) * 4);
    float4 t1 = *(const float4*)(aw + (256 + c4 + 1) * 4);
    float4 t2 = *(const float4*)(aw + (256 + c4 + 2) * 4);
    float4 t3 = *(const float4*)(aw + (256 + c4 + 3) * 4);
    const float wa0 = t0.x + t0.y + t0.z + t0.w;
    const float wa1 = t1.x + t1.y + t1.z + t1.w;
    const float wa2 = t2.x + t2.y + t2.z + t2.w;
    const float wa3 = t3.x + t3.y + t3.z + t3.w;
#pragma unroll 1
    for (int rr = 0; rr < 8; rr++) {
        const int row = wid * 8 + rr;
        float4 v = *(const float4*)(X + row * 132 + c4);
        float mean = wred(v.x + v.y + v.z + v.w) * (1.f / 128.f);
        float dx = v.x - mean, dy = v.y - mean, dz = v.z - mean, dw = v.w - mean;
        float var = wred(dx * dx + dy * dy + dz * dz + dw * dw) * (1.f / 128.f);
        float rstd = rsqrtf(var + 1e-5f);
        float4 y;
        y.x = dx * rstd * g4.x + b4.x;
        y.y = dy * rstd * g4.y + b4.y;
        y.z = dz * rstd * g4.z + b4.z;
        y.w = dw * rstd * g4.w + b4.w;
        *(float4*)(e_out + (size_t)(e0 + row) * 128 + c4) = y;
        float sp = wred(y.x * wa0 + y.y * wa1 + y.z * wa2 + y.w * wa3);
        if (lane == 0) {
            int dd = didx[row];
            float sc = sp * 0.25f + g_node_score[dd] + abm;
            g_scores[e0 + row] = sc;
            atomicMax(&g_segmax[dd], f2o(sc));
        }
    }
}

// ---------------- K2: ex = exp(score - segmax[dst]); se[dst] += ex ----------------
__global__ void k2_exp(const int* __restrict__ ei) {
    int e = blockIdx.x * 256 + threadIdx.x;
    if (e >= EE) return;
    int d = ei[EE + e];
    float ex = expf(g_scores[e] - o2f(g_segmax[d]));
    g_ex[e] = ex;
    atomicAdd(&g_se[d], ex);
}

// ---------------- K3: agg[dst] += w_e * e_e ----------------
__global__ void k3_scatter(const int* __restrict__ ei, const float* __restrict__ e_feat) {
    int e = blockIdx.x * 2 + (threadIdx.x >> 7);
    int c = threadIdx.x & 127;
    int d = ei[EE + e];
    float w = g_ex[e] / (g_se[d] + 1e-6f);
    atomicAdd(&g_agg[(size_t)d * 128 + c], w * e_feat[(size_t)e * 128 + c]);
}

// ---------------- K4: node update (3 fused GEMMs + residual + LN), f32x2 ----------------
template <int KDIM, int NCOLS>
__device__ __forceinline__ void gemm_smem(const float* Xs, int ldx,
                                          const float* __restrict__ Bg,
                                          float* Bs, ull* acc, int tid) {
    constexpr int NP = NCOLS / 32;
    const int tx = tid & 15, ty = tid >> 4;
#pragma unroll 1
    for (int k0 = 0; k0 < KDIM; k0 += 16) {
        __syncthreads();
        constexpr int NF4 = 16 * NCOLS / 4;
#pragma unroll
        for (int j = 0; j < NF4 / 256; j++) {
            int f = tid + j * 256;
            int rr = f / (NCOLS / 4);
            int cc = (f - rr * (NCOLS / 4)) * 4;
            *(float4*)(Bs + rr * NCOLS + cc) = *(const float4*)(Bg + (size_t)(k0 + rr) * NCOLS + cc);
        }
        __syncthreads();
#pragma unroll
        for (int kk = 0; kk < 16; kk++) {
            ull aa[4];
#pragma unroll
            for (int i = 0; i < 4; i++) { float a = Xs[(ty * 4 + i) * ldx + k0 + kk]; aa[i] = pk(a, a); }
#pragma unroll
            for (int p = 0; p < NP; p++) {
                ull bb = *(const ull*)(Bs + kk * NCOLS + (tx + 16 * p) * 2);
#pragma unroll
                for (int i = 0; i < 4; i++) fma2(acc[i * NP + p], aa[i], bb);
            }
        }
    }
    __syncthreads();
}

__global__ __launch_bounds__(256, 2) void k4_node(
    const float* __restrict__ nf,
    const float* __restrict__ evw, const float* __restrict__ evb,
    const float* __restrict__ ow1, const float* __restrict__ ob1,
    const float* __restrict__ ow2, const float* __restrict__ ob2,
    const float* __restrict__ nng, const float* __restrict__ nnb,
    float* __restrict__ n_out) {
    extern __shared__ float sm[];
    float* X  = sm;              // 64*256
    float* Bs = X + 64 * 256;    // 16*256
    float* sw = Bs + 16 * 256;   // 64
    const int tid = threadIdx.x;
    const int tx = tid & 15, ty = tid >> 4;
    const int n0 = blockIdx.x * 64;
#pragma unroll
    for (int j = 0; j < 8; j++) {
        int f = tid + j * 256;
        int rr = f >> 5; int cc = (f & 31) * 4;
        float4 v = make_float4(0.f, 0.f, 0.f, 0.f);
        if (n0 + rr < NN) v = *(const float4*)(g_agg + (size_t)(n0 + rr) * 128 + cc);
        *(float4*)(X + rr * 128 + cc) = v;
    }
    if (tid < 64) {
        int nn2 = n0 + tid;
        float se = (nn2 < NN) ? g_se[nn2] : 0.f;
        sw[tid] = se / (se + 1e-6f);
    }
    ull acc[32];
#pragma unroll
    for (int i = 0; i < 32; i++) acc[i] = 0ull;
    gemm_smem<128, 256>(X, 128, evw, Bs, acc, tid);
#pragma unroll
    for (int i = 0; i < 4; i++) {
        int rr = ty * 4 + i;
        float s = sw[rr];
#pragma unroll
        for (int p = 0; p < 8; p++) {
            int c0 = (tx + 16 * p) * 2;
            float2 v = upk(acc[i * 8 + p]);
            v.x += s * evb[c0];
            v.y += s * evb[c0 + 1];
            *(float2*)(X + rr * 256 + c0) = v;
        }
    }
#pragma unroll
    for (int i = 0; i < 32; i++) acc[i] = 0ull;
    gemm_smem<256, 256>(X, 256, ow1, Bs, acc, tid);
#pragma unroll
    for (int i = 0; i < 4; i++) {
        int rr = ty * 4 + i;
#pragma unroll
        for (int p = 0; p < 8; p++) {
            int c0 = (tx + 16 * p) * 2;
            float2 v = upk(acc[i * 8 + p]);
            v.x = fmaxf(v.x + ob1[c0], 0.f);
            v.y = fmaxf(v.y + ob1[c0 + 1], 0.f);
            *(float2*)(X + rr * 256 + c0) = v;
        }
    }
#pragma unroll
    for (int i = 0; i < 32; i++) acc[i] = 0ull;
    gemm_smem<256, 256>(X, 256, ow2, Bs, acc, tid);
#pragma unroll
    for (int i = 0; i < 4; i++) {
        int rr = ty * 4 + i;
        int row = n0 + rr;
#pragma unroll
        for (int p = 0; p < 8; p++) {
            int c0 = (tx + 16 * p) * 2;
            float2 v = upk(acc[i * 8 + p]);
            v.x += ob2[c0];
            v.y += ob2[c0 + 1];
            if (row < NN) {
                v.x += nf[(size_t)row * 256 + c0];
                v.y += nf[(size_t)row * 256 + c0 + 1];
            }
            *(float2*)(X + rr * 256 + c0) = v;
        }
    }
    __syncthreads();
    const int wp = tid >> 5, lane = tid & 31;
    const int cb = lane * 8;
    float4 g0 = *(const float4*)(nng + cb), g1 = *(const float4*)(nng + cb + 4);
    float4 h0 = *(const float4*)(nnb + cb), h1 = *(const float4*)(nnb + cb + 4);
#pragma unroll 1
    for (int rr = 0; rr < 8; rr++) {
        int rrow = wp * 8 + rr;
        int row = n0 + rrow;
        float4 v0 = *(const float4*)(X + rrow * 256 + cb);
        float4 v1 = *(const float4*)(X + rrow * 256 + cb + 4);
        float mean = wred(v0.x + v0.y + v0.z + v0.w + v1.x + v1.y + v1.z + v1.w) * (1.f / 256.f);
        float d0x = v0.x - mean, d0y = v0.y - mean, d0z = v0.z - mean, d0w = v0.w - mean;
        float d1x = v1.x - mean, d1y = v1.y - mean, d1z = v1.z - mean, d1w = v1.w - mean;
        float var = wred(d0x * d0x + d0y * d0y + d0z * d0z + d0w * d0w +
                         d1x * d1x + d1y * d1y + d1z * d1z + d1w * d1w) * (1.f / 256.f);
        float rstd = rsqrtf(var + 1e-5f);
        if (row < NN) {
            float4 y0, y1;
            y0.x = d0x * rstd * g0.x + h0.x; y0.y = d0y * rstd * g0.y + h0.y;
            y0.z = d0z * rstd * g0.z + h0.z; y0.w = d0w * rstd * g0.w + h0.w;
            y1.x = d1x * rstd * g1.x + h1.x; y1.y = d1y * rstd * g1.y + h1.y;
            y1.z = d1z * rstd * g1.z + h1.z; y1.w = d1w * rstd * g1.w + h1.w;
            *(float4*)(n_out + (size_t)row * 256 + cb) = y0;
            *(float4*)(n_out + (size_t)row * 256 + cb + 4) = y1;
        }
    }
}

// ---------------- launch ----------------
extern "C" void kernel_launch(void* const* d_in, const int* in_sizes, int n_in,
                              void* d_out, int out_size) {
    const float* nf  = (const float*)d_in[0];
    const float* ef  = (const float*)d_in[1];
    const int*   ei  = (const int*)d_in[2];
    const float* ew1 = (const float*)d_in[3];
    const float* eb1 = (const float*)d_in[4];
    const float* ew2 = (const float*)d_in[5];
    const float* eb2 = (const float*)d_in[6];
    const float* eng = (const float*)d_in[7];
    const float* enb = (const float*)d_in[8];
    const float* aw  = (const float*)d_in[9];
    const float* ab  = (const float*)d_in[10];
    const float* evw = (const float*)d_in[11];
    const float* evb = (const float*)d_in[12];
    const float* ow1 = (const float*)d_in[13];
    const float* ob1 = (const float*)d_in[14];
    const float* ow2 = (const float*)d_in[15];
    const float* ob2 = (const float*)d_in[16];
    const float* nng = (const float*)d_in[17];
    const float* nnb = (const float*)d_in[18];

    float* out = (float*)d_out;
    float* n_out = out;                        // (N, 256)
    float* e_out = out + (size_t)NN * 256;     // (E, 128)

    const int SMEM4 = (64 * 256 + 16 * 256 + 64) * 4;
    cudaFuncSetAttribute(k1_edge_mma, cudaFuncAttributeMaxDynamicSharedMemorySize, SMEM_K1);
    cudaFuncSetAttribute(k4_node, cudaFuncAttributeMaxDynamicSharedMemorySize, SMEM4);

    k_prep<<<768, 256>>>(ew1, ew2);
    k0_node_prep<<<(NN + 7) / 8, 256>>>(nf, aw);
    k1_edge_mma<<<TILES64, 256, SMEM_K1>>>(nf, ef, ei, eb1, eb2, eng, enb, aw, ab, e_out);
    k2_exp<<<(EE + 255) / 256, 256>>>(ei);
    k3_scatter<<<EE / 2, 256>>>(ei, e_out);
    k4_node<<<(NN + 63) / 64, 256, SMEM4>>>(nf, evw, evb, ow1, ob1, ow2, ob2, nng, nnb, n_out);
}

// round 16
// speedup vs baseline: 1.0957x; 1.0957x over previous
#include <cuda_runtime.h>
#include <cuda_bf16.h>
#include <cuda_fp16.h>
#include <cstdint>

#define NN 25000
#define EE 400000
#define TILES64 (EE / 64)   // 6250

typedef unsigned long long ull;

// ---- scratch (static device globals; no allocation) ----
__device__ float g_node_score[NN];
__device__ int   g_segmax[NN];
__device__ float g_se[NN];
__device__ float g_agg[(size_t)NN * 128];
__device__ float g_scores[EE];
__device__ float g_ex[EE];
// transposed fp16 weights, K-major [N][K]
__device__ __half g_w1t16[256 * 640];
__device__ __half g_w2t16[128 * 256];

// ---- generic helpers ----
__device__ __forceinline__ ull pk(float lo, float hi) {
    ull r; asm("mov.b64 %0, {%1,%2};" : "=l"(r) : "f"(lo), "f"(hi)); return r;
}
__device__ __forceinline__ float2 upk(ull v) {
    float2 r; asm("mov.b64 {%0,%1}, %2;" : "=f"(r.x), "=f"(r.y) : "l"(v)); return r;
}
__device__ __forceinline__ void fma2(ull& d, ull a, ull b) {
    asm("fma.rn.f32x2 %0, %1, %2, %0;" : "+l"(d) : "l"(a), "l"(b));
}
__device__ __forceinline__ float wred(float v) {
#pragma unroll
    for (int o = 16; o; o >>= 1) v += __shfl_xor_sync(0xffffffffu, v, o);
    return v;
}
__device__ __forceinline__ int f2o(float f) { int i = __float_as_int(f); return i >= 0 ? i : i ^ 0x7fffffff; }
__device__ __forceinline__ float o2f(int i) { return __int_as_float(i >= 0 ? i : i ^ 0x7fffffff); }
__device__ __forceinline__ uint32_t smem_u32(const void* p) {
    uint32_t a; asm("{ .reg .u64 t; cvta.to.shared.u64 t, %1; cvt.u32.u64 %0, t; }" : "=r"(a) : "l"(p));
    return a;
}
__device__ __forceinline__ uint32_t h2u(__half2 h) { return *(uint32_t*)&h; }

// warp-level fp16 MMA (sm_80+ baseline PTX; valid on plain sm_100 target)
__device__ __forceinline__ void mma16816(float* d, const uint32_t* a, uint32_t b0, uint32_t b1) {
    asm volatile(
        "mma.sync.aligned.m16n8k16.row.col.f32.f16.f16.f32 "
        "{%0,%1,%2,%3}, {%4,%5,%6,%7}, {%8,%9}, {%0,%1,%2,%3};"
        : "+f"(d[0]), "+f"(d[1]), "+f"(d[2]), "+f"(d[3])
        : "r"(a[0]), "r"(a[1]), "r"(a[2]), "r"(a[3]), "r"(b0), "r"(b1));
}

// ldmatrix x4 (sm_75+ baseline)
__device__ __forceinline__ void ldmx4(uint32_t* r, uint32_t addr) {
    asm volatile("ldmatrix.sync.aligned.m8n8.x4.shared.b16 {%0,%1,%2,%3}, [%4];"
                 : "=r"(r[0]), "=r"(r[1]), "=r"(r[2]), "=r"(r[3]) : "r"(addr));
}

// ---------------- prep: transpose fp16 weights ----------------
__global__ void k_prep(const float* __restrict__ ew1, const float* __restrict__ ew2) {
    int i = blockIdx.x * 256 + threadIdx.x;
    if (i < 256 * 640) {
        int n = i / 640, k = i - n * 640;
        g_w1t16[i] = __float2half_rn(ew1[(size_t)k * 256 + n]);
    } else {
        int j = i - 256 * 640;
        if (j < 128 * 256) {
            int n = j / 256, k = j - n * 256;
            g_w2t16[j] = __float2half_rn(ew2[(size_t)k * 128 + n]);
        }
    }
}

// ---------------- K0: per-node attention-score part + scratch init ----------------
__global__ void k0_node_prep(const float* __restrict__ nf, const float* __restrict__ aw) {
    int node = blockIdx.x * 8 + (threadIdx.x >> 5);
    int lane = threadIdx.x & 31;
    if (node >= NN) return;
    const float* row = nf + (size_t)node * 256;
    float s = 0.f;
#pragma unroll
    for (int c = lane; c < 256; c += 32) {
        const float4 a = *(const float4*)(aw + c * 4);
        s += row[c] * (a.x + a.y + a.z + a.w);
    }
    s = wred(s);
    if (lane == 0) {
        g_node_score[node] = s * 0.25f;
        g_segmax[node] = (int)0x80000000;
        g_se[node] = 0.f;
    }
    *(float4*)(g_agg + (size_t)node * 128 + lane * 4) = make_float4(0.f, 0.f, 0.f, 0.f);
}

// ---------------- K1: 64-edge tiles, single-pass fp16, occ=2 (proven R13) ----------------
// SMEM (bytes), rows padded to 72 fp16 (144B = 9x16B granules, conflict-free):
//  0:     sidx[64] | 256: didx[64]
//  1024:  A    [64][72]   (9216)
//  10240: B    [128][72]  (18432)
//  28672: H: 4 K-chunks x [64][72] = 36864    (also X fp32 [64][132] = 33792 in epilogue2)
//  total 65536
#define OFF_A  1024
#define OFF_B  10240
#define OFF_H  28672
#define OFF_X  28672
#define SMEM_K1 65536

// single-pass MMA over one 64-K chunk: acc += A*B
__device__ __forceinline__ void mma_chunk1(float acc[2][4][4], uint32_t shA, uint32_t shB) {
#pragma unroll
    for (int ks = 0; ks < 4; ks++) {
        const uint32_t kb2 = ks * 32;  // k bytes
        uint32_t Aa[2][4];
        ldmx4(Aa[0], shA + kb2);
        ldmx4(Aa[1], shA + 2304 + kb2);
#pragma unroll
        for (int ntp = 0; ntp < 2; ntp++) {
            uint32_t b[4];
            ldmx4(b, shB + ntp * 2304 + kb2);
#pragma unroll
            for (int hf = 0; hf < 2; hf++) {
                const int nt = ntp * 2 + hf;
                mma16816(acc[0][nt], Aa[0], b[hf * 2], b[hf * 2 + 1]);
                mma16816(acc[1][nt], Aa[1], b[hf * 2], b[hf * 2 + 1]);
            }
        }
    }
}

__global__ __launch_bounds__(256, 2) void k1_edge_mma(
    const float* __restrict__ nf, const float* __restrict__ ef, const int* __restrict__ ei,
    const float* __restrict__ eb1, const float* __restrict__ eb2,
    const float* __restrict__ eng, const float* __restrict__ enb,
    const float* __restrict__ aw, const float* __restrict__ ab,
    float* __restrict__ e_out) {
    extern __shared__ char smb[];
    int* sidx = (int*)smb;
    int* didx = (int*)(smb + 256);
    const int tid = threadIdx.x;
    const int wid = tid >> 5, lane = tid & 31;
    const int wm = wid >> 2, wn = wid & 3;
    const int m0 = wm * 32;
    const int qr = lane >> 2;         // 0..7
    const int qc = (lane & 3) * 2;    // 0,2,4,6
    const int e0 = blockIdx.x * 64;

    if (tid < 64) sidx[tid] = ei[e0 + tid];
    else if (tid < 128) didx[tid - 64] = ei[EE + e0 + tid - 64];
    __syncthreads();

    const uint32_t sbase = smem_u32(smb);
    const int mrow = (lane & 7) + (((lane >> 3) & 1) << 3);
    const uint32_t aOff = (uint32_t)((m0 + mrow) * 144 + ((lane >> 4) << 4));
    const int brow = (lane & 7) + ((lane >> 4) << 3);
    const uint32_t bOff = (uint32_t)((wn * 32 + brow) * 144 + (((lane >> 3) & 1) << 4));
    const uint32_t shA = sbase + OFF_A + aOff;
    const uint32_t shB = sbase + OFF_B + bOff;

    float4 pfA[4];
    uint4  pfW[4];
    const int arow = tid >> 2, akc = (tid & 3) * 16;
    const int wrow = tid >> 1, wkc = (tid & 1) * 32;

    auto ldA = [&](int c) {
        const int kg = c * 64 + akc;
        const float* base;
        if (kg < 256)      base = nf + (size_t)sidx[arow] * 256 + kg;
        else if (kg < 512) base = nf + (size_t)didx[arow] * 256 + (kg - 256);
        else               base = ef + (size_t)(e0 + arow) * 128 + (kg - 512);
#pragma unroll
        for (int g = 0; g < 4; g++) pfA[g] = *(const float4*)(base + g * 4);
    };
    auto ldW1 = [&](int h, int c) {
        const __half* src = g_w1t16 + (size_t)(h * 128 + wrow) * 640 + c * 64 + wkc;
#pragma unroll
        for (int g = 0; g < 4; g++) pfW[g] = *(const uint4*)(src + g * 8);
    };
    auto ldW2 = [&](int c) {
        const __half* src = g_w2t16 + (size_t)wrow * 256 + c * 64 + wkc;
#pragma unroll
        for (int g = 0; g < 4; g++) pfW[g] = *(const uint4*)(src + g * 8);
    };
    auto stA = [&]() {
        uint32_t hv[8];
#pragma unroll
        for (int g = 0; g < 4; g++) {
            float4 v = pfA[g];
            hv[g * 2]     = h2u(__floats2half2_rn(v.x, v.y));
            hv[g * 2 + 1] = h2u(__floats2half2_rn(v.z, v.w));
        }
        const uint32_t off = (uint32_t)(arow * 144 + akc * 2);
        *(uint4*)(smb + OFF_A + off)      = make_uint4(hv[0], hv[1], hv[2], hv[3]);
        *(uint4*)(smb + OFF_A + off + 16) = make_uint4(hv[4], hv[5], hv[6], hv[7]);
    };
    auto stW = [&]() {
        char* dst = smb + OFF_B + wrow * 144 + wkc * 2;
#pragma unroll
        for (int g = 0; g < 4; g++) *(uint4*)(dst + g * 16) = pfW[g];
    };

    float acc[2][4][4];
#pragma unroll
    for (int mt = 0; mt < 2; mt++)
#pragma unroll
        for (int nt = 0; nt < 4; nt++)
#pragma unroll
            for (int q = 0; q < 4; q++) acc[mt][nt][q] = 0.f;

    // ========= phase 1: 20 pipelined chunks (2 N-halves x 10 K-chunks) =========
    ldA(0); ldW1(0, 0);
#pragma unroll 1
    for (int st = 0; st < 20; st++) {
        const int h = st / 10, c = st % 10;
        __syncthreads();
        stA(); stW();
        __syncthreads();
        if (st < 19) { ldA((st + 1) % 10); ldW1((st + 1) / 10, (st + 1) % 10); }
        else ldW2(0);
        mma_chunk1(acc, shA, shB);
        if (c == 9) {
            const int chunk = h * 2 + (wn >> 1);
            char* Hh = smb + OFF_H + chunk * 9216;
#pragma unroll
            for (int mt = 0; mt < 2; mt++)
#pragma unroll
                for (int nt = 0; nt < 4; nt++) {
                    const int gcol = h * 128 + wn * 32 + nt * 8 + qc;
                    const float b0v = eb1[gcol], b1v = eb1[gcol + 1];
                    const int row = m0 + mt * 16 + qr;
                    const int colc = (wn & 1) * 32 + nt * 8 + qc;
                    float f0 = fmaxf(acc[mt][nt][0] + b0v, 0.f);
                    float f1 = fmaxf(acc[mt][nt][1] + b1v, 0.f);
                    *(uint32_t*)(Hh + row * 144 + colc * 2) = h2u(__floats2half2_rn(f0, f1));
                    float f2 = fmaxf(acc[mt][nt][2] + b0v, 0.f);
                    float f3 = fmaxf(acc[mt][nt][3] + b1v, 0.f);
                    *(uint32_t*)(Hh + (row + 8) * 144 + colc * 2) = h2u(__floats2half2_rn(f2, f3));
                }
#pragma unroll
            for (int mt = 0; mt < 2; mt++)
#pragma unroll
                for (int nt = 0; nt < 4; nt++)
#pragma unroll
                    for (int q = 0; q < 4; q++) acc[mt][nt][q] = 0.f;
        }
    }

    // ========= phase 2: H(64x256) @ W2(256x128), 4 pipelined chunks =========
#pragma unroll 1
    for (int c2 = 0; c2 < 4; c2++) {
        __syncthreads();
        stW();
        __syncthreads();
        if (c2 < 3) ldW2(c2 + 1);
        const uint32_t shH = sbase + OFF_H + c2 * 9216 + aOff;
        mma_chunk1(acc, shH, shB);
    }

    // ========= epilogue 2: bias + residual -> X, LN, score =========
    __syncthreads();
    float* X = (float*)(smb + OFF_X);
#pragma unroll
    for (int mt = 0; mt < 2; mt++)
#pragma unroll
        for (int nt = 0; nt < 4; nt++) {
            const int col = wn * 32 + nt * 8 + qc;
            const float b0v = eb2[col], b1v = eb2[col + 1];
            const int row = m0 + mt * 16 + qr;
            float2 v0, v1;
            v0.x = acc[mt][nt][0] + b0v + ef[(size_t)(e0 + row) * 128 + col];
            v0.y = acc[mt][nt][1] + b1v + ef[(size_t)(e0 + row) * 128 + col + 1];
            v1.x = acc[mt][nt][2] + b0v + ef[(size_t)(e0 + row + 8) * 128 + col];
            v1.y = acc[mt][nt][3] + b1v + ef[(size_t)(e0 + row + 8) * 128 + col + 1];
            *(float2*)(X + row * 132 + col) = v0;
            *(float2*)(X + (row + 8) * 132 + col) = v1;
        }
    __syncthreads();

    const float abm = 0.25f * (ab[0] + ab[1] + ab[2] + ab[3]);
    const int c4 = lane * 4;
    const float4 g4 = *(const float4*)(eng + c4);
    const float4 b4 = *(const float4*)(enb + c4);
    float4 t0 = *(const float4*)(aw + (256 + c4) * 4);
    float4 t1 = *(const float4*)(aw + (256 + c4 + 1) * 4);
    float4 t2 = *(const float4*)(aw + (256 + c4 + 2) * 4);
    float4 t3 = *(const float4*)(aw + (256 + c4 + 3) * 4);
    const float wa0 = t0.x + t0.y + t0.z + t0.w;
    const float wa1 = t1.x + t1.y + t1.z + t1.w;
    const float wa2 = t2.x + t2.y + t2.z + t2.w;
    const float wa3 = t3.x + t3.y + t3.z + t3.w;
#pragma unroll 1
    for (int rr = 0; rr < 8; rr++) {
        const int row = wid * 8 + rr;
        float4 v = *(const float4*)(X + row * 132 + c4);
        float mean = wred(v.x + v.y + v.z + v.w) * (1.f / 128.f);
        float dx = v.x - mean, dy = v.y - mean, dz = v.z - mean, dw = v.w - mean;
        float var = wred(dx * dx + dy * dy + dz * dz + dw * dw) * (1.f / 128.f);
        float rstd = rsqrtf(var + 1e-5f);
        float4 y;
        y.x = dx * rstd * g4.x + b4.x;
        y.y = dy * rstd * g4.y + b4.y;
        y.z = dz * rstd * g4.z + b4.z;
        y.w = dw * rstd * g4.w + b4.w;
        *(float4*)(e_out + (size_t)(e0 + row) * 128 + c4) = y;
        float sp = wred(y.x * wa0 + y.y * wa1 + y.z * wa2 + y.w * wa3);
        if (lane == 0) {
            int dd = didx[row];
            float sc = sp * 0.25f + g_node_score[dd] + abm;
            g_scores[e0 + row] = sc;
            atomicMax(&g_segmax[dd], f2o(sc));
        }
    }
}

// ---------------- K2: ex = exp(score - segmax[dst]); se[dst] += ex ----------------
__global__ void k2_exp(const int* __restrict__ ei) {
    int e = blockIdx.x * 256 + threadIdx.x;
    if (e >= EE) return;
    int d = ei[EE + e];
    float ex = expf(g_scores[e] - o2f(g_segmax[d]));
    g_ex[e] = ex;
    atomicAdd(&g_se[d], ex);
}

// ---------------- K3: agg[dst] += ex_e * e_e (normalization deferred to K4) ----------------
__global__ void k3_scatter(const int* __restrict__ ei, const float* __restrict__ e_feat) {
    int t = blockIdx.x * 256 + threadIdx.x;
    int e = t >> 5;
    int c = (t & 31) * 4;
    int d = ei[EE + e];
    float w = g_ex[e];
    float4 v = *(const float4*)(e_feat + (size_t)e * 128 + c);
    float* dst = g_agg + (size_t)d * 128 + c;
    atomicAdd(dst + 0, w * v.x);
    atomicAdd(dst + 1, w * v.y);
    atomicAdd(dst + 2, w * v.z);
    atomicAdd(dst + 3, w * v.w);
}

// ---------------- K4: node update (3 fused GEMMs + residual + LN), f32x2 ----------------
template <int KDIM, int NCOLS>
__device__ __forceinline__ void gemm_smem(const float* Xs, int ldx,
                                          const float* __restrict__ Bg,
                                          float* Bs, ull* acc, int tid) {
    constexpr int NP = NCOLS / 32;
    const int tx = tid & 15, ty = tid >> 4;
#pragma unroll 1
    for (int k0 = 0; k0 < KDIM; k0 += 16) {
        __syncthreads();
        constexpr int NF4 = 16 * NCOLS / 4;
#pragma unroll
        for (int j = 0; j < NF4 / 256; j++) {
            int f = tid + j * 256;
            int rr = f / (NCOLS / 4);
            int cc = (f - rr * (NCOLS / 4)) * 4;
            *(float4*)(Bs + rr * NCOLS + cc) = *(const float4*)(Bg + (size_t)(k0 + rr) * NCOLS + cc);
        }
        __syncthreads();
#pragma unroll
        for (int kk = 0; kk < 16; kk++) {
            ull aa[4];
#pragma unroll
            for (int i = 0; i < 4; i++) { float a = Xs[(ty * 4 + i) * ldx + k0 + kk]; aa[i] = pk(a, a); }
#pragma unroll
            for (int p = 0; p < NP; p++) {
                ull bb = *(const ull*)(Bs + kk * NCOLS + (tx + 16 * p) * 2);
#pragma unroll
                for (int i = 0; i < 4; i++) fma2(acc[i * NP + p], aa[i], bb);
            }
        }
    }
    __syncthreads();
}

__global__ __launch_bounds__(256, 2) void k4_node(
    const float* __restrict__ nf,
    const float* __restrict__ evw, const float* __restrict__ evb,
    const float* __restrict__ ow1, const float* __restrict__ ob1,
    const float* __restrict__ ow2, const float* __restrict__ ob2,
    const float* __restrict__ nng, const float* __restrict__ nnb,
    float* __restrict__ n_out) {
    extern __shared__ float sm[];
    float* X    = sm;              // 64*256
    float* Bs   = X + 64 * 256;    // 16*256
    float* sw   = Bs + 16 * 256;   // 64
    float* sinv = sw + 64;         // 64
    const int tid = threadIdx.x;
    const int tx = tid & 15, ty = tid >> 4;
    const int n0 = blockIdx.x * 64;
#pragma unroll
    for (int j = 0; j < 8; j++) {
        int f = tid + j * 256;
        int rr = f >> 5; int cc = (f & 31) * 4;
        float4 v = make_float4(0.f, 0.f, 0.f, 0.f);
        if (n0 + rr < NN) v = *(const float4*)(g_agg + (size_t)(n0 + rr) * 128 + cc);
        *(float4*)(X + rr * 128 + cc) = v;
    }
    if (tid < 64) {
        int nn2 = n0 + tid;
        float se = (nn2 < NN) ? g_se[nn2] : 0.f;
        float inv = 1.f / (se + 1e-6f);
        sw[tid] = se * inv;
        sinv[tid] = inv;
    }
    ull acc[32];
#pragma unroll
    for (int i = 0; i < 32; i++) acc[i] = 0ull;
    // messages = (agg @ evw) * inv + sw * evb
    gemm_smem<128, 256>(X, 128, evw, Bs, acc, tid);
#pragma unroll
    for (int i = 0; i < 4; i++) {
        int rr = ty * 4 + i;
        float s = sw[rr], inv = sinv[rr];
#pragma unroll
        for (int p = 0; p < 8; p++) {
            int c0 = (tx + 16 * p) * 2;
            float2 v = upk(acc[i * 8 + p]);
            v.x = v.x * inv + s * evb[c0];
            v.y = v.y * inv + s * evb[c0 + 1];
            *(float2*)(X + rr * 256 + c0) = v;
        }
    }
#pragma unroll
    for (int i = 0; i < 32; i++) acc[i] = 0ull;
    gemm_smem<256, 256>(X, 256, ow1, Bs, acc, tid);
#pragma unroll
    for (int i = 0; i < 4; i++) {
        int rr = ty * 4 + i;
#pragma unroll
        for (int p = 0; p < 8; p++) {
            int c0 = (tx + 16 * p) * 2;
            float2 v = upk(acc[i * 8 + p]);
            v.x = fmaxf(v.x + ob1[c0], 0.f);
            v.y = fmaxf(v.y + ob1[c0 + 1], 0.f);
            *(float2*)(X + rr * 256 + c0) = v;
        }
    }
#pragma unroll
    for (int i = 0; i < 32; i++) acc[i] = 0ull;
    gemm_smem<256, 256>(X, 256, ow2, Bs, acc, tid);
#pragma unroll
    for (int i = 0; i < 4; i++) {
        int rr = ty * 4 + i;
        int row = n0 + rr;
#pragma unroll
        for (int p = 0; p < 8; p++) {
            int c0 = (tx + 16 * p) * 2;
            float2 v = upk(acc[i * 8 + p]);
            v.x += ob2[c0];
            v.y += ob2[c0 + 1];
            if (row < NN) {
                v.x += nf[(size_t)row * 256 + c0];
                v.y += nf[(size_t)row * 256 + c0 + 1];
            }
            *(float2*)(X + rr * 256 + c0) = v;
        }
    }
    __syncthreads();
    const int wp = tid >> 5, lane = tid & 31;
    const int cb = lane * 8;
    float4 g0 = *(const float4*)(nng + cb), g1 = *(const float4*)(nng + cb + 4);
    float4 h0 = *(const float4*)(nnb + cb), h1 = *(const float4*)(nnb + cb + 4);
#pragma unroll 1
    for (int rr = 0; rr < 8; rr++) {
        int rrow = wp * 8 + rr;
        int row = n0 + rrow;
        float4 v0 = *(const float4*)(X + rrow * 256 + cb);
        float4 v1 = *(const float4*)(X + rrow * 256 + cb + 4);
        float mean = wred(v0.x + v0.y + v0.z + v0.w + v1.x + v1.y + v1.z + v1.w) * (1.f / 256.f);
        float d0x = v0.x - mean, d0y = v0.y - mean, d0z = v0.z - mean, d0w = v0.w - mean;
        float d1x = v1.x - mean, d1y = v1.y - mean, d1z = v1.z - mean, d1w = v1.w - mean;
        float var = wred(d0x * d0x + d0y * d0y + d0z * d0z + d0w * d0w +
                         d1x * d1x + d1y * d1y + d1z * d1z + d1w * d1w) * (1.f / 256.f);
        float rstd = rsqrtf(var + 1e-5f);
        if (row < NN) {
            float4 y0, y1;
            y0.x = d0x * rstd * g0.x + h0.x; y0.y = d0y * rstd * g0.y + h0.y;
            y0.z = d0z * rstd * g0.z + h0.z; y0.w = d0w * rstd * g0.w + h0.w;
            y1.x = d1x * rstd * g1.x + h1.x; y1.y = d1y * rstd * g1.y + h1.y;
            y1.z = d1z * rstd * g1.z + h1.z; y1.w = d1w * rstd * g1.w + h1.w;
            *(float4*)(n_out + (size_t)row * 256 + cb) = y0;
            *(float4*)(n_out + (size_t)row * 256 + cb + 4) = y1;
        }
    }
}

// ---------------- launch ----------------
extern "C" void kernel_launch(void* const* d_in, const int* in_sizes, int n_in,
                              void* d_out, int out_size) {
    const float* nf  = (const float*)d_in[0];
    const float* ef  = (const float*)d_in[1];
    const int*   ei  = (const int*)d_in[2];
    const float* ew1 = (const float*)d_in[3];
    const float* eb1 = (const float*)d_in[4];
    const float* ew2 = (const float*)d_in[5];
    const float* eb2 = (const float*)d_in[6];
    const float* eng = (const float*)d_in[7];
    const float* enb = (const float*)d_in[8];
    const float* aw  = (const float*)d_in[9];
    const float* ab  = (const float*)d_in[10];
    const float* evw = (const float*)d_in[11];
    const float* evb = (const float*)d_in[12];
    const float* ow1 = (const float*)d_in[13];
    const float* ob1 = (const float*)d_in[14];
    const float* ow2 = (const float*)d_in[15];
    const float* ob2 = (const float*)d_in[16];
    const float* nng = (const float*)d_in[17];
    const float* nnb = (const float*)d_in[18];

    float* out = (float*)d_out;
    float* n_out = out;                        // (N, 256)
    float* e_out = out + (size_t)NN * 256;     // (E, 128)

    const int SMEM4 = (64 * 256 + 16 * 256 + 128) * 4;
    cudaFuncSetAttribute(k1_edge_mma, cudaFuncAttributeMaxDynamicSharedMemorySize, SMEM_K1);
    cudaFuncSetAttribute(k4_node, cudaFuncAttributeMaxDynamicSharedMemorySize, SMEM4);

    k_prep<<<768, 256>>>(ew1, ew2);
    k0_node_prep<<<(NN + 7) / 8, 256>>>(nf, aw);
    k1_edge_mma<<<TILES64, 256, SMEM_K1>>>(nf, ef, ei, eb1, eb2, eng, enb, aw, ab, e_out);
    k2_exp<<<(EE + 255) / 256, 256>>>(ei);
    k3_scatter<<<EE / 8, 256>>>(ei, e_out);
    k4_node<<<(NN + 63) / 64, 256, SMEM4>>>(nf, evw, evb, ow1, ob1, ow2, ob2, nng, nnb, n_out);
}